// round 10
// baseline (speedup 1.0000x reference)
#include <cuda_runtime.h>
#include <math.h>

// Lin2d: x <- x @ Mt, 1000 times, Mt = [[c,-s],[s,c]] (float32 c,s).
// Collapsed to one complex multiply by w = (c - i*s)^1000 (host double math).
// Streaming kernel: 4 independent float4s per thread (front-batched, MLP=4),
// evict-first cache hints (__ldcs/__stcs) since each byte is touched once.

__global__ void lin2d_apply_kernel(const float4* __restrict__ in,
                                   float4* __restrict__ out,
                                   int n4, float wr, float wi) {
    const int bd = blockDim.x;
    int base = blockIdx.x * (bd * 4) + threadIdx.x;
    int i0 = base;
    int i1 = base + bd;
    int i2 = base + 2 * bd;
    int i3 = base + 3 * bd;

    if (i3 < n4) {
        // Fast path: full tile (all blocks when n4 % (4*bd) == 0).
        float4 v0 = __ldcs(in + i0);
        float4 v1 = __ldcs(in + i1);
        float4 v2 = __ldcs(in + i2);
        float4 v3 = __ldcs(in + i3);

        float4 r0, r1, r2, r3;
        r0.x = fmaf(wr, v0.x, -wi * v0.y);
        r0.y = fmaf(wi, v0.x,  wr * v0.y);
        r0.z = fmaf(wr, v0.z, -wi * v0.w);
        r0.w = fmaf(wi, v0.z,  wr * v0.w);
        r1.x = fmaf(wr, v1.x, -wi * v1.y);
        r1.y = fmaf(wi, v1.x,  wr * v1.y);
        r1.z = fmaf(wr, v1.z, -wi * v1.w);
        r1.w = fmaf(wi, v1.z,  wr * v1.w);
        r2.x = fmaf(wr, v2.x, -wi * v2.y);
        r2.y = fmaf(wi, v2.x,  wr * v2.y);
        r2.z = fmaf(wr, v2.z, -wi * v2.w);
        r2.w = fmaf(wi, v2.z,  wr * v2.w);
        r3.x = fmaf(wr, v3.x, -wi * v3.y);
        r3.y = fmaf(wi, v3.x,  wr * v3.y);
        r3.z = fmaf(wr, v3.z, -wi * v3.w);
        r3.w = fmaf(wi, v3.z,  wr * v3.w);

        __stcs(out + i0, r0);
        __stcs(out + i1, r1);
        __stcs(out + i2, r2);
        __stcs(out + i3, r3);
    } else {
        // Tail path (never taken for this problem size; kept for safety).
        #pragma unroll
        for (int k = 0; k < 4; k++) {
            int i = base + k * bd;
            if (i < n4) {
                float4 v = __ldcs(in + i);
                float4 r;
                r.x = fmaf(wr, v.x, -wi * v.y);
                r.y = fmaf(wi, v.x,  wr * v.y);
                r.z = fmaf(wr, v.z, -wi * v.w);
                r.w = fmaf(wi, v.z,  wr * v.w);
                __stcs(out + i, r);
            }
        }
    }
}

extern "C" void kernel_launch(void* const* d_in, const int* in_sizes, int n_in,
                              void* d_out, int out_size) {
    const float* x = (const float*)d_in[0];
    float* y = (float*)d_out;
    const int n = in_sizes[0];       // total floats = BATCH*2 (multiple of 4)
    const int n4 = n / 4;

    // Host-side constants (pure math at capture time; deterministic).
    const double theta = 3.14159265358979323846 / 100.0;
    const double c = (double)((float)cos(theta));
    const double s = (double)((float)sin(theta));
    const int N = 1000;
    const double r   = hypot(c, s);
    const double phi = atan2(s, c);
    const double mag = pow(r, (double)N);
    // w = (c - i*s)^N = mag * (cos(N*phi) - i*sin(N*phi))
    const float wr = (float)(mag * cos((double)N * phi));
    const float wi = (float)(-mag * sin((double)N * phi));

    const int threads = 256;
    const int per_block = threads * 4;
    const int blocks = (n4 + per_block - 1) / per_block;
    lin2d_apply_kernel<<<blocks, threads>>>((const float4*)x, (float4*)y,
                                            n4, wr, wi);
}